// round 5
// baseline (speedup 1.0000x reference)
#include <cuda_runtime.h>
#include <cstdint>

typedef unsigned long long ull;

#define NSEQ 480
#define TLEN 200
#define CH   64
#define HID  128
#define G4   512
#define NROW (NSEQ * TLEN)   // 96000

// ---------------- device scratch ----------------
__device__ float g_xf[NROW * CH];      // [t*480+seq][c]
__device__ float g_xg[NROW * G4];      // [t*480+seq][g]
__device__ float g_Wp[HID * HID * 4];  // [k][r][{i,f,g,o}]
__device__ float g_Wiht[CH * G4];      // [c][g]
__device__ float g_bias[G4];

// ---------------- helpers ----------------
__device__ __forceinline__ ull pk2(float lo, float hi) {
    ull r; asm("mov.b64 %0, {%1, %2};" : "=l"(r) : "f"(lo), "f"(hi)); return r;
}
__device__ __forceinline__ void upk2(ull v, float& lo, float& hi) {
    asm("mov.b64 {%0, %1}, %2;" : "=f"(lo), "=f"(hi) : "l"(v));
}
__device__ __forceinline__ void fma2(ull& a, ull b, ull c) {
    asm("fma.rn.f32x2 %0, %1, %2, %0;" : "+l"(a) : "l"(b), "l"(c));
}
__device__ __forceinline__ void add2(ull& a, ull b) {
    asm("add.rn.f32x2 %0, %0, %1;" : "+l"(a) : "l"(b));
}
__device__ __forceinline__ float tanh_t(float x) {
    float t; asm("tanh.approx.f32 %0, %1;" : "=f"(t) : "f"(x)); return t;
}
__device__ __forceinline__ ull shfl2(ull v, int m) {
    uint32_t lo = (uint32_t)v, hi = (uint32_t)(v >> 32);
    lo = __shfl_xor_sync(0xffffffffu, lo, m);
    hi = __shfl_xor_sync(0xffffffffu, hi, m);
    return ((ull)hi << 32) | lo;
}

// ---------------- prep ----------------
__global__ void __launch_bounds__(256) prep_kernel(
    const float* __restrict__ Wih, const float* __restrict__ Whh,
    const float* __restrict__ bih, const float* __restrict__ bhh)
{
    int idx = blockIdx.x * 256 + threadIdx.x;
    if (idx < HID * HID * 4) {
        int qg = idx & 3, r = (idx >> 2) & 127, k = idx >> 9;
        g_Wp[idx] = Whh[(qg * 128 + r) * 128 + k];
    }
    if (idx < CH * G4) {
        int c = idx >> 9, g = idx & 511;
        g_Wiht[idx] = Wih[g * 64 + c];
    }
    if (idx < G4) g_bias[idx] = bih[idx] + bhh[idx];
}

// ---------------- transpose x: (B,C,T,P) -> xf[t*480 + b*30+p][c] ----------------
__global__ void __launch_bounds__(256) transp_kernel(const float* __restrict__ x)
{
    __shared__ float tile[64 * 30];
    int t = blockIdx.x, b = blockIdx.y;
    for (int idx = threadIdx.x; idx < 64 * 30; idx += 256) {
        int c = idx / 30, p = idx - c * 30;
        tile[idx] = x[(b * 64 + c) * 6000 + t * 30 + p];
    }
    __syncthreads();
    for (int idx = threadIdx.x; idx < 64 * 30; idx += 256) {
        int p = idx >> 6, c = idx & 63;
        g_xf[(t * NSEQ + b * 30 + p) * 64 + c] = tile[c * 30 + p];
    }
}

// ---------------- xg GEMM: 128x128 tile, 8x8 microtile ----------------
#define AS(k, m) As[(k) * 132 + (m)]
#define BS(k, n) Bs[(k) * 128 + (n)]
#define GEMM_SMEM (64 * 132 * 4 + 64 * 128 * 4)

__global__ void __launch_bounds__(256, 2) gemm_kernel()
{
    extern __shared__ float As[];
    float* Bs = As + 64 * 132;
    int tid = threadIdx.x;
    int row0 = blockIdx.x * 128, col0 = blockIdx.y * 128;

    for (int i = tid; i < 2048; i += 256) {
        int m = i >> 4, k4 = i & 15;
        float4 v = *(const float4*)&g_xf[(row0 + m) * 64 + k4 * 4];
        AS(k4 * 4 + 0, m) = v.x;
        AS(k4 * 4 + 1, m) = v.y;
        AS(k4 * 4 + 2, m) = v.z;
        AS(k4 * 4 + 3, m) = v.w;
    }
    for (int i = tid; i < 2048; i += 256) {
        int k = i >> 5, n4 = i & 31;
        *(float4*)&BS(k, n4 * 4) = *(const float4*)&g_Wiht[k * 512 + col0 + n4 * 4];
    }
    __syncthreads();

    int tm = tid & 15, tn = tid >> 4;
    int m0 = tm * 8, n0 = tn * 8;
    ull acc[8][4];
#pragma unroll
    for (int i = 0; i < 8; i++)
#pragma unroll
        for (int j = 0; j < 4; j++) acc[i][j] = 0;

#pragma unroll 8
    for (int k = 0; k < 64; k++) {
        float4 a0 = *(const float4*)&AS(k, m0);
        float4 a1 = *(const float4*)&AS(k, m0 + 4);
        longlong2 bv0 = *(const longlong2*)&BS(k, n0);
        longlong2 bv1 = *(const longlong2*)&BS(k, n0 + 4);
        ull b[4] = {(ull)bv0.x, (ull)bv0.y, (ull)bv1.x, (ull)bv1.y};
        float am[8] = {a0.x, a0.y, a0.z, a0.w, a1.x, a1.y, a1.z, a1.w};
#pragma unroll
        for (int i = 0; i < 8; i++) {
            ull ad = pk2(am[i], am[i]);
            fma2(acc[i][0], b[0], ad);
            fma2(acc[i][1], b[1], ad);
            fma2(acc[i][2], b[2], ad);
            fma2(acc[i][3], b[3], ad);
        }
    }

    float4 bi0 = *(const float4*)&g_bias[col0 + n0];
    float4 bi1 = *(const float4*)&g_bias[col0 + n0 + 4];
    float bn[8] = {bi0.x, bi0.y, bi0.z, bi0.w, bi1.x, bi1.y, bi1.z, bi1.w};
#pragma unroll
    for (int i = 0; i < 8; i++) {
        float v[8];
        upk2(acc[i][0], v[0], v[1]); upk2(acc[i][1], v[2], v[3]);
        upk2(acc[i][2], v[4], v[5]); upk2(acc[i][3], v[6], v[7]);
        float* dst = &g_xg[(size_t)(row0 + m0 + i) * 512 + col0 + n0];
        *(float4*)dst       = make_float4(v[0] + bn[0], v[1] + bn[1], v[2] + bn[2], v[3] + bn[3]);
        *(float4*)(dst + 4) = make_float4(v[4] + bn[4], v[5] + bn[5], v[6] + bn[6], v[7] + bn[7]);
    }
}

// ---------------- persistent LSTM + FC ----------------
// Lane mapping: l = tid&31, q = l&3 (k-quarter AND owned seq), r = (tid>>5)*8 + (l>>2)
// h buffers: 2 x 512 ull; h[k][s] at ull index (k&31)*16 + (k>>5)*4 + s, value (h,h)
#define LS_WS   0                        // 64*128 longlong2 (128 KB)
#define LS_XB   (128 * 1024)             // 2*512 float4 (16 KB): xg double buffer
#define LS_HD   (LS_XB + 16384)          // 2*512 ull (8 KB): h double buffer
#define LS_TOTAL (LS_HD + 8192)          // 155648 B

__global__ void __launch_bounds__(512, 1) lstm_kernel(
    const float* __restrict__ Wfc, const float* __restrict__ bfc,
    float* __restrict__ out)
{
    extern __shared__ char smem[];
    longlong2* Ws2 = (longlong2*)(smem + LS_WS);
    float4*    xb4 = (float4*)(smem + LS_XB);
    ull*       hd  = (ull*)(smem + LS_HD);

    int tid = threadIdx.x;
    int l = tid & 31;
    int q  = l & 3;                  // k-quarter, and owned seq
    int q2 = q * 2;
    int r  = (tid >> 5) * 8 + (l >> 2);
    int s0 = blockIdx.x * 4;

    // register half of W_hh: k in [32q, 32q+16)
    ull WIF[16], WGO[16];
    const longlong2* Wp2 = (const longlong2*)g_Wp;
#pragma unroll
    for (int kk = 0; kk < 16; kk++) {
        longlong2 v = Wp2[(32 * q + kk) * 128 + r];
        WIF[kk] = (ull)v.x; WGO[kk] = (ull)v.y;
    }
    // smem half: k in [32q+16, 32q+32), layout [(qq*16+kk-16)][rr]
    for (int idx = tid; idx < 64 * 128; idx += 512) {
        int kidx = idx >> 7, rr = idx & 127;
        int qq = kidx >> 4, kk = (kidx & 15) + 16;
        Ws2[idx] = Wp2[(32 * qq + kk) * 128 + rr];
    }

    hd[tid] = 0ull;
    hd[tid + 512] = 0ull;
    const float4* xg4 = (const float4*)g_xg;
    xb4[tid] = xg4[(size_t)s0 * 128 + tid];   // t=0 -> buffer 0

    float cst = 0.f;   // c-state for (row r, seq q)
    int hsti = (r & 31) * 16 + (r >> 5) * 4 + q;   // h store slot
    __syncthreads();

#pragma unroll 1
    for (int t = 0; t < TLEN; t++) {
        float4 nx = make_float4(0.f, 0.f, 0.f, 0.f);
        if (t + 1 < TLEN) nx = xg4[((size_t)(t + 1) * NSEQ + s0) * 128 + tid];

        const longlong2* hb2 = (const longlong2*)(hd + (t & 1) * 512);

        ull aIF0 = 0, aIF1 = 0, aIF2 = 0, aIF3 = 0;
        ull aGO0 = 0, aGO1 = 0, aGO2 = 0, aGO3 = 0;

#pragma unroll
        for (int kk = 0; kk < 16; kk++) {            // register-W half (k=32q+kk)
            longlong2 hA = hb2[kk * 8 + q2];         // (h,h) s=0,1
            longlong2 hB = hb2[kk * 8 + q2 + 1];     // (h,h) s=2,3
            ull h0 = (ull)hA.x, h1 = (ull)hA.y, h2 = (ull)hB.x, h3 = (ull)hB.y;
            fma2(aIF0, WIF[kk], h0); fma2(aGO0, WGO[kk], h0);
            fma2(aIF1, WIF[kk], h1); fma2(aGO1, WGO[kk], h1);
            fma2(aIF2, WIF[kk], h2); fma2(aGO2, WGO[kk], h2);
            fma2(aIF3, WIF[kk], h3); fma2(aGO3, WGO[kk], h3);
        }
#pragma unroll
        for (int kk = 0; kk < 16; kk++) {            // smem-W half (k=32q+16+kk)
            longlong2 wv = Ws2[(q * 16 + kk) * 128 + r];
            ull wIF = (ull)wv.x, wGO = (ull)wv.y;
            longlong2 hA = hb2[(kk + 16) * 8 + q2];
            longlong2 hB = hb2[(kk + 16) * 8 + q2 + 1];
            ull h0 = (ull)hA.x, h1 = (ull)hA.y, h2 = (ull)hB.x, h3 = (ull)hB.y;
            fma2(aIF0, wIF, h0); fma2(aGO0, wGO, h0);
            fma2(aIF1, wIF, h1); fma2(aGO1, wGO, h1);
            fma2(aIF2, wIF, h2); fma2(aGO2, wGO, h2);
            fma2(aIF3, wIF, h3); fma2(aGO3, wGO, h3);
        }

        // gate-x loads early (hide latency under shuffles)
        const float* xb = (const float*)&xb4[(t & 1) * 512];
        float xi = xb[q * 512 + r];
        float xf = xb[q * 512 + 128 + r];
        float xg_ = xb[q * 512 + 256 + r];
        float xo = xb[q * 512 + 384 + r];

        // butterfly reduce over the 4 q-lanes (lane q keeps seq q)
        bool loH = (q < 2);
        ull kIF0 = loH ? aIF0 : aIF2;
        ull kIF1 = loH ? aIF1 : aIF3;
        ull sIF0 = loH ? aIF2 : aIF0;
        ull sIF1 = loH ? aIF3 : aIF1;
        ull kGO0 = loH ? aGO0 : aGO2;
        ull kGO1 = loH ? aGO1 : aGO3;
        ull sGO0 = loH ? aGO2 : aGO0;
        ull sGO1 = loH ? aGO3 : aGO1;
        add2(kIF0, shfl2(sIF0, 2));
        add2(kIF1, shfl2(sIF1, 2));
        add2(kGO0, shfl2(sGO0, 2));
        add2(kGO1, shfl2(sGO1, 2));
        bool evq = !(q & 1);
        ull kIF = evq ? kIF0 : kIF1;
        ull sIF = evq ? kIF1 : kIF0;
        ull kGO = evq ? kGO0 : kGO1;
        ull sGO = evq ? kGO1 : kGO0;
        add2(kIF, shfl2(sIF, 1));
        add2(kGO, shfl2(sGO, 1));

        float gi, gf, gg, go;
        upk2(kIF, gi, gf); upk2(kGO, gg, go);
        gi += xi; gf += xf; gg += xg_; go += xo;

        float i_ = 0.5f * tanh_t(0.5f * gi) + 0.5f;
        float f_ = 0.5f * tanh_t(0.5f * gf) + 0.5f;
        float o_ = 0.5f * tanh_t(0.5f * go) + 0.5f;
        float g_ = tanh_t(gg);

        cst = f_ * cst + i_ * g_;
        float th = tanh_t(cst);
        float hv = o_ * th;

        hd[((t + 1) & 1) * 512 + hsti] = pk2(hv, hv);
        if (t + 1 < TLEN) xb4[((t + 1) & 1) * 512 + tid] = nx;
        __syncthreads();
    }

    // ---- FC epilogue (h final in buffer 0; reuse Ws2 region for W_fc^T) ----
    float* wfs = (float*)(smem + LS_WS);
    for (int idx = tid; idx < CH * HID; idx += 512) {
        int c = idx >> 7, j = idx & 127;
        wfs[j * 64 + c] = Wfc[idx];
    }
    __syncthreads();
    if (tid < 256) {
        int c = tid & 63, s = tid >> 6;
        float acc = bfc[c];
#pragma unroll 8
        for (int j = 0; j < HID; j++) {
            float hj, dummy;
            upk2(hd[(j & 31) * 16 + (j >> 5) * 4 + s], hj, dummy);
            acc += hj * wfs[j * 64 + c];
        }
        out[(s0 + s) * 64 + c] = acc;
    }
}

// ---------------- launch ----------------
extern "C" void kernel_launch(void* const* d_in, const int* in_sizes, int n_in,
                              void* d_out, int out_size)
{
    const float* x   = (const float*)d_in[0];
    const float* Wih = (const float*)d_in[1];
    const float* Whh = (const float*)d_in[2];
    const float* bih = (const float*)d_in[3];
    const float* bhh = (const float*)d_in[4];
    const float* Wfc = (const float*)d_in[5];
    const float* bfc = (const float*)d_in[6];
    float* out = (float*)d_out;

    cudaFuncSetAttribute(gemm_kernel, cudaFuncAttributeMaxDynamicSharedMemorySize, GEMM_SMEM);
    cudaFuncSetAttribute(lstm_kernel, cudaFuncAttributeMaxDynamicSharedMemorySize, LS_TOTAL);

    prep_kernel<<<256, 256>>>(Wih, Whh, bih, bhh);
    transp_kernel<<<dim3(TLEN, 16), 256>>>(x);
    gemm_kernel<<<dim3(NROW / 128, G4 / 128), 256, GEMM_SMEM>>>();
    lstm_kernel<<<120, 512, LS_TOTAL>>>(Wfc, bfc, out);
}

// round 6
// speedup vs baseline: 1.5104x; 1.5104x over previous
#include <cuda_runtime.h>
#include <cstdint>

typedef unsigned long long ull;

#define NSEQ 480
#define TLEN 200
#define CH   64
#define HID  128
#define G4   512
#define NROW (NSEQ * TLEN)   // 96000

// ---------------- device scratch ----------------
__device__ float g_xf[NROW * CH];      // [t*480+seq][c]
__device__ float g_xg[NROW * G4];      // [t*480+seq][g]
__device__ float g_Wp[HID * HID * 4];  // [k][r][{i,f,g,o}]
__device__ float g_Wiht[CH * G4];      // [c][g]
__device__ float g_bias[G4];

// ---------------- helpers ----------------
__device__ __forceinline__ ull pk2(float lo, float hi) {
    ull r; asm("mov.b64 %0, {%1, %2};" : "=l"(r) : "f"(lo), "f"(hi)); return r;
}
__device__ __forceinline__ void upk2(ull v, float& lo, float& hi) {
    asm("mov.b64 {%0, %1}, %2;" : "=f"(lo), "=f"(hi) : "l"(v));
}
__device__ __forceinline__ void fma2(ull& a, ull b, ull c) {
    asm("fma.rn.f32x2 %0, %1, %2, %0;" : "+l"(a) : "l"(b), "l"(c));
}
__device__ __forceinline__ void add2(ull& a, ull b) {
    asm("add.rn.f32x2 %0, %0, %1;" : "+l"(a) : "l"(b));
}
__device__ __forceinline__ float tanh_t(float x) {
    float t; asm("tanh.approx.f32 %0, %1;" : "=f"(t) : "f"(x)); return t;
}
__device__ __forceinline__ ull shfl2(ull v, int m) {
    uint32_t lo = (uint32_t)v, hi = (uint32_t)(v >> 32);
    lo = __shfl_xor_sync(0xffffffffu, lo, m);
    hi = __shfl_xor_sync(0xffffffffu, hi, m);
    return ((ull)hi << 32) | lo;
}

// ---------------- prep ----------------
__global__ void __launch_bounds__(256) prep_kernel(
    const float* __restrict__ Wih, const float* __restrict__ Whh,
    const float* __restrict__ bih, const float* __restrict__ bhh)
{
    int idx = blockIdx.x * 256 + threadIdx.x;
    if (idx < HID * HID * 4) {
        int qg = idx & 3, r = (idx >> 2) & 127, k = idx >> 9;
        g_Wp[idx] = Whh[(qg * 128 + r) * 128 + k];
    }
    if (idx < CH * G4) {
        int c = idx >> 9, g = idx & 511;
        g_Wiht[idx] = Wih[g * 64 + c];
    }
    if (idx < G4) g_bias[idx] = bih[idx] + bhh[idx];
}

// ---------------- transpose x: (B,C,T,P) -> xf[t*480 + b*30+p][c] ----------------
__global__ void __launch_bounds__(256) transp_kernel(const float* __restrict__ x)
{
    __shared__ float tile[64 * 30];
    int t = blockIdx.x, b = blockIdx.y;
    for (int idx = threadIdx.x; idx < 64 * 30; idx += 256) {
        int c = idx / 30, p = idx - c * 30;
        tile[idx] = x[(b * 64 + c) * 6000 + t * 30 + p];
    }
    __syncthreads();
    for (int idx = threadIdx.x; idx < 64 * 30; idx += 256) {
        int p = idx >> 6, c = idx & 63;
        g_xf[(t * NSEQ + b * 30 + p) * 64 + c] = tile[c * 30 + p];
    }
}

// ---------------- xg GEMM: 128x128 tile, 8x8 microtile ----------------
#define AS(k, m) As[(k) * 132 + (m)]
#define BS(k, n) Bs[(k) * 128 + (n)]
#define GEMM_SMEM (64 * 132 * 4 + 64 * 128 * 4)

__global__ void __launch_bounds__(256, 2) gemm_kernel()
{
    extern __shared__ float As[];
    float* Bs = As + 64 * 132;
    int tid = threadIdx.x;
    int row0 = blockIdx.x * 128, col0 = blockIdx.y * 128;

    for (int i = tid; i < 2048; i += 256) {
        int m = i >> 4, k4 = i & 15;
        float4 v = *(const float4*)&g_xf[(row0 + m) * 64 + k4 * 4];
        AS(k4 * 4 + 0, m) = v.x;
        AS(k4 * 4 + 1, m) = v.y;
        AS(k4 * 4 + 2, m) = v.z;
        AS(k4 * 4 + 3, m) = v.w;
    }
    for (int i = tid; i < 2048; i += 256) {
        int k = i >> 5, n4 = i & 31;
        *(float4*)&BS(k, n4 * 4) = *(const float4*)&g_Wiht[k * 512 + col0 + n4 * 4];
    }
    __syncthreads();

    int tm = tid & 15, tn = tid >> 4;
    int m0 = tm * 8, n0 = tn * 8;
    ull acc[8][4];
#pragma unroll
    for (int i = 0; i < 8; i++)
#pragma unroll
        for (int j = 0; j < 4; j++) acc[i][j] = 0;

#pragma unroll 8
    for (int k = 0; k < 64; k++) {
        float4 a0 = *(const float4*)&AS(k, m0);
        float4 a1 = *(const float4*)&AS(k, m0 + 4);
        longlong2 bv0 = *(const longlong2*)&BS(k, n0);
        longlong2 bv1 = *(const longlong2*)&BS(k, n0 + 4);
        ull b[4] = {(ull)bv0.x, (ull)bv0.y, (ull)bv1.x, (ull)bv1.y};
        float am[8] = {a0.x, a0.y, a0.z, a0.w, a1.x, a1.y, a1.z, a1.w};
#pragma unroll
        for (int i = 0; i < 8; i++) {
            ull ad = pk2(am[i], am[i]);
            fma2(acc[i][0], b[0], ad);
            fma2(acc[i][1], b[1], ad);
            fma2(acc[i][2], b[2], ad);
            fma2(acc[i][3], b[3], ad);
        }
    }

    float4 bi0 = *(const float4*)&g_bias[col0 + n0];
    float4 bi1 = *(const float4*)&g_bias[col0 + n0 + 4];
    float bn[8] = {bi0.x, bi0.y, bi0.z, bi0.w, bi1.x, bi1.y, bi1.z, bi1.w};
#pragma unroll
    for (int i = 0; i < 8; i++) {
        float v[8];
        upk2(acc[i][0], v[0], v[1]); upk2(acc[i][1], v[2], v[3]);
        upk2(acc[i][2], v[4], v[5]); upk2(acc[i][3], v[6], v[7]);
        float* dst = &g_xg[(size_t)(row0 + m0 + i) * 512 + col0 + n0];
        *(float4*)dst       = make_float4(v[0] + bn[0], v[1] + bn[1], v[2] + bn[2], v[3] + bn[3]);
        *(float4*)(dst + 4) = make_float4(v[4] + bn[4], v[5] + bn[5], v[6] + bn[6], v[7] + bn[7]);
    }
}

// ---------------- persistent LSTM + FC ----------------
// Lane mapping: l = tid&31, q = l&3 (k-quarter AND owned seq), r = (tid>>5)*8 + (l>>2)
// Ws2 (smem W half, k=32q+16+kk): longlong2 index (kk*128 + r)*4 + q  -> lane-consecutive
// h buffers: 2 x 512 ull; h[k][s] at ull index (k&31)*16 + (k>>5)*4 + s, value (h,h)
// xb buffers: 2 x (4 seqs x 520 floats)  (520 = 512+8: bank-spread q-stride)
#define XB_S 520
#define LS_WS   0                        // 8192 longlong2 (128 KB)
#define LS_XB   (128 * 1024)             // 2*4*520 floats (16640 B)
#define LS_HD   (LS_XB + 16640)          // 2*512 ull (8 KB)
#define LS_TOTAL (LS_HD + 8192)

__global__ void __launch_bounds__(512, 1) lstm_kernel(
    const float* __restrict__ Wfc, const float* __restrict__ bfc,
    float* __restrict__ out)
{
    extern __shared__ char smem[];
    longlong2* Ws2 = (longlong2*)(smem + LS_WS);
    float*     xbf = (float*)(smem + LS_XB);
    ull*       hd  = (ull*)(smem + LS_HD);

    int tid = threadIdx.x;
    int l = tid & 31;
    int q  = l & 3;                  // k-quarter, and owned seq
    int q2 = q * 2;
    int r  = (tid >> 5) * 8 + (l >> 2);
    int s0 = blockIdx.x * 4;

    // register half of W_hh: k in [32q, 32q+16)
    ull WIF[16], WGO[16];
    const longlong2* Wp2 = (const longlong2*)g_Wp;
#pragma unroll
    for (int kk = 0; kk < 16; kk++) {
        longlong2 v = Wp2[(32 * q + kk) * 128 + r];
        WIF[kk] = (ull)v.x; WGO[kk] = (ull)v.y;
    }
    // smem half: k in [32q+16, 32q+32), interleaved layout (kk*128+r)*4+q
    for (int idx = tid; idx < 8192; idx += 512) {
        int kk = idx >> 9, rr = (idx & 511) >> 2, qq = idx & 3;
        Ws2[idx] = Wp2[(32 * qq + 16 + kk) * 128 + rr];
    }

    hd[tid] = 0ull;
    hd[tid + 512] = 0ull;
    const float4* xg4 = (const float4*)g_xg;
    // preload t=0 -> xb buffer 0; thread tid carries seq (tid>>7), gates (tid&127)*4..+3
    {
        float4 v = xg4[(size_t)s0 * 128 + tid];
        int s = tid >> 7, g = (tid & 127) * 4;
        *(float4*)&xbf[s * XB_S + g] = v;
    }

    float cst = 0.f;   // c-state for (row r, seq q)
    int hsti = (r & 31) * 16 + (r >> 5) * 4 + q;   // h store slot
    __syncthreads();

#pragma unroll 1
    for (int t = 0; t < TLEN; t++) {
        float4 nx = make_float4(0.f, 0.f, 0.f, 0.f);
        if (t + 1 < TLEN) nx = xg4[((size_t)(t + 1) * NSEQ + s0) * 128 + tid];

        const longlong2* hb2 = (const longlong2*)(hd + (t & 1) * 512);

        ull aIF0 = 0, aIF1 = 0, aIF2 = 0, aIF3 = 0;
        ull aGO0 = 0, aGO1 = 0, aGO2 = 0, aGO3 = 0;

#pragma unroll
        for (int kk = 0; kk < 16; kk++) {            // register-W half (k=32q+kk)
            longlong2 hA = hb2[kk * 8 + q2];         // (h,h) s=0,1
            longlong2 hB = hb2[kk * 8 + q2 + 1];     // (h,h) s=2,3
            ull h0 = (ull)hA.x, h1 = (ull)hA.y, h2 = (ull)hB.x, h3 = (ull)hB.y;
            fma2(aIF0, WIF[kk], h0); fma2(aGO0, WGO[kk], h0);
            fma2(aIF1, WIF[kk], h1); fma2(aGO1, WGO[kk], h1);
            fma2(aIF2, WIF[kk], h2); fma2(aGO2, WGO[kk], h2);
            fma2(aIF3, WIF[kk], h3); fma2(aGO3, WGO[kk], h3);
        }
#pragma unroll
        for (int kk = 0; kk < 16; kk++) {            // smem-W half (k=32q+16+kk)
            longlong2 wv = Ws2[(kk * 128 + r) * 4 + q];
            ull wIF = (ull)wv.x, wGO = (ull)wv.y;
            longlong2 hA = hb2[(kk + 16) * 8 + q2];
            longlong2 hB = hb2[(kk + 16) * 8 + q2 + 1];
            ull h0 = (ull)hA.x, h1 = (ull)hA.y, h2 = (ull)hB.x, h3 = (ull)hB.y;
            fma2(aIF0, wIF, h0); fma2(aGO0, wGO, h0);
            fma2(aIF1, wIF, h1); fma2(aGO1, wGO, h1);
            fma2(aIF2, wIF, h2); fma2(aGO2, wGO, h2);
            fma2(aIF3, wIF, h3); fma2(aGO3, wGO, h3);
        }

        // gate-x loads early (conflict-free: XB_S % 32 == 8)
        const float* xb = &xbf[((t & 1) ? (4 * XB_S) : 0)];
        float xi  = xb[q * XB_S + r];
        float xf  = xb[q * XB_S + 128 + r];
        float xg_ = xb[q * XB_S + 256 + r];
        float xo  = xb[q * XB_S + 384 + r];

        // butterfly reduce over the 4 q-lanes (lane q keeps seq q)
        bool loH = (q < 2);
        ull kIF0 = loH ? aIF0 : aIF2;
        ull kIF1 = loH ? aIF1 : aIF3;
        ull sIF0 = loH ? aIF2 : aIF0;
        ull sIF1 = loH ? aIF3 : aIF1;
        ull kGO0 = loH ? aGO0 : aGO2;
        ull kGO1 = loH ? aGO1 : aGO3;
        ull sGO0 = loH ? aGO2 : aGO0;
        ull sGO1 = loH ? aGO3 : aGO1;
        add2(kIF0, shfl2(sIF0, 2));
        add2(kIF1, shfl2(sIF1, 2));
        add2(kGO0, shfl2(sGO0, 2));
        add2(kGO1, shfl2(sGO1, 2));
        bool evq = !(q & 1);
        ull kIF = evq ? kIF0 : kIF1;
        ull sIF = evq ? kIF1 : kIF0;
        ull kGO = evq ? kGO0 : kGO1;
        ull sGO = evq ? kGO1 : kGO0;
        add2(kIF, shfl2(sIF, 1));
        add2(kGO, shfl2(sGO, 1));

        float gi, gf, gg, go;
        upk2(kIF, gi, gf); upk2(kGO, gg, go);
        gi += xi; gf += xf; gg += xg_; go += xo;

        float i_ = 0.5f * tanh_t(0.5f * gi) + 0.5f;
        float f_ = 0.5f * tanh_t(0.5f * gf) + 0.5f;
        float o_ = 0.5f * tanh_t(0.5f * go) + 0.5f;
        float g_ = tanh_t(gg);

        cst = f_ * cst + i_ * g_;
        float th = tanh_t(cst);
        float hv = o_ * th;

        hd[((t + 1) & 1) * 512 + hsti] = pk2(hv, hv);
        if (t + 1 < TLEN) {
            int s = tid >> 7, g = (tid & 127) * 4;
            *(float4*)&xbf[((t + 1) & 1) * (4 * XB_S) + s * XB_S + g] = nx;
        }
        __syncthreads();
    }

    // ---- FC epilogue (h final in buffer (TLEN&1)=0; reuse Ws2 region for W_fc^T) ----
    float* wfs = (float*)(smem + LS_WS);
    for (int idx = tid; idx < CH * HID; idx += 512) {
        int c = idx >> 7, j = idx & 127;
        wfs[j * 64 + c] = Wfc[idx];
    }
    __syncthreads();
    if (tid < 256) {
        int c = tid & 63, s = tid >> 6;
        float acc = bfc[c];
#pragma unroll 8
        for (int j = 0; j < HID; j++) {
            float hj, dummy;
            upk2(hd[(j & 31) * 16 + (j >> 5) * 4 + s], hj, dummy);
            acc += hj * wfs[j * 64 + c];
        }
        out[(s0 + s) * 64 + c] = acc;
    }
}

// ---------------- launch ----------------
extern "C" void kernel_launch(void* const* d_in, const int* in_sizes, int n_in,
                              void* d_out, int out_size)
{
    const float* x   = (const float*)d_in[0];
    const float* Wih = (const float*)d_in[1];
    const float* Whh = (const float*)d_in[2];
    const float* bih = (const float*)d_in[3];
    const float* bhh = (const float*)d_in[4];
    const float* Wfc = (const float*)d_in[5];
    const float* bfc = (const float*)d_in[6];
    float* out = (float*)d_out;

    cudaFuncSetAttribute(gemm_kernel, cudaFuncAttributeMaxDynamicSharedMemorySize, GEMM_SMEM);
    cudaFuncSetAttribute(lstm_kernel, cudaFuncAttributeMaxDynamicSharedMemorySize, LS_TOTAL);

    prep_kernel<<<256, 256>>>(Wih, Whh, bih, bhh);
    transp_kernel<<<dim3(TLEN, 16), 256>>>(x);
    gemm_kernel<<<dim3(NROW / 128, G4 / 128), 256, GEMM_SMEM>>>();
    lstm_kernel<<<120, 512, LS_TOTAL>>>(Wfc, bfc, out);
}

// round 7
// speedup vs baseline: 2.0654x; 1.3674x over previous
#include <cuda_runtime.h>
#include <cstdint>

typedef unsigned long long ull;

#define NSEQ 480
#define TLEN 200
#define CH   64
#define HID  128
#define G4   512
#define NROW (NSEQ * TLEN)   // 96000

// ---------------- device scratch ----------------
__device__ float g_xf[NROW * CH];      // [t*480+seq][c]
__device__ float g_xg[NROW * G4];      // [t*480+seq][g]
__device__ float g_Wp[HID * HID * 4];  // [k][r][{i,f,g,o}]
__device__ float g_Wiht[CH * G4];      // [c][g]
__device__ float g_bias[G4];

// ---------------- helpers ----------------
__device__ __forceinline__ ull pk2(float lo, float hi) {
    ull r; asm("mov.b64 %0, {%1, %2};" : "=l"(r) : "f"(lo), "f"(hi)); return r;
}
__device__ __forceinline__ void upk2(ull v, float& lo, float& hi) {
    asm("mov.b64 {%0, %1}, %2;" : "=f"(lo), "=f"(hi) : "l"(v));
}
__device__ __forceinline__ void fma2(ull& a, ull b, ull c) {
    asm("fma.rn.f32x2 %0, %1, %2, %0;" : "+l"(a) : "l"(b), "l"(c));
}
__device__ __forceinline__ void add2(ull& a, ull b) {
    asm("add.rn.f32x2 %0, %0, %1;" : "+l"(a) : "l"(b));
}
__device__ __forceinline__ float tanh_t(float x) {
    float t; asm("tanh.approx.f32 %0, %1;" : "=f"(t) : "f"(x)); return t;
}

// ---------------- prep ----------------
__global__ void __launch_bounds__(256) prep_kernel(
    const float* __restrict__ Wih, const float* __restrict__ Whh,
    const float* __restrict__ bih, const float* __restrict__ bhh)
{
    int idx = blockIdx.x * 256 + threadIdx.x;
    if (idx < HID * HID * 4) {
        int qg = idx & 3, r = (idx >> 2) & 127, k = idx >> 9;
        g_Wp[idx] = Whh[(qg * 128 + r) * 128 + k];
    }
    if (idx < CH * G4) {
        int c = idx >> 9, g = idx & 511;
        g_Wiht[idx] = Wih[g * 64 + c];
    }
    if (idx < G4) g_bias[idx] = bih[idx] + bhh[idx];
}

// ---------------- transpose x: (B,C,T,P) -> xf[t*480 + b*30+p][c] ----------------
__global__ void __launch_bounds__(256) transp_kernel(const float* __restrict__ x)
{
    __shared__ float tile[64 * 30];
    int t = blockIdx.x, b = blockIdx.y;
    for (int idx = threadIdx.x; idx < 64 * 30; idx += 256) {
        int c = idx / 30, p = idx - c * 30;
        tile[idx] = x[(b * 64 + c) * 6000 + t * 30 + p];
    }
    __syncthreads();
    for (int idx = threadIdx.x; idx < 64 * 30; idx += 256) {
        int p = idx >> 6, c = idx & 63;
        g_xf[(t * NSEQ + b * 30 + p) * 64 + c] = tile[c * 30 + p];
    }
}

// ---------------- xg GEMM: 128x128 tile, 8x8 microtile ----------------
#define AS(k, m) As[(k) * 132 + (m)]
#define BS(k, n) Bs[(k) * 128 + (n)]
#define GEMM_SMEM (64 * 132 * 4 + 64 * 128 * 4)

__global__ void __launch_bounds__(256, 2) gemm_kernel()
{
    extern __shared__ float As[];
    float* Bs = As + 64 * 132;
    int tid = threadIdx.x;
    int row0 = blockIdx.x * 128, col0 = blockIdx.y * 128;

    for (int i = tid; i < 2048; i += 256) {
        int m = i >> 4, k4 = i & 15;
        float4 v = *(const float4*)&g_xf[(row0 + m) * 64 + k4 * 4];
        AS(k4 * 4 + 0, m) = v.x;
        AS(k4 * 4 + 1, m) = v.y;
        AS(k4 * 4 + 2, m) = v.z;
        AS(k4 * 4 + 3, m) = v.w;
    }
    for (int i = tid; i < 2048; i += 256) {
        int k = i >> 5, n4 = i & 31;
        *(float4*)&BS(k, n4 * 4) = *(const float4*)&g_Wiht[k * 512 + col0 + n4 * 4];
    }
    __syncthreads();

    int tm = tid & 15, tn = tid >> 4;
    int m0 = tm * 8, n0 = tn * 8;
    ull acc[8][4];
#pragma unroll
    for (int i = 0; i < 8; i++)
#pragma unroll
        for (int j = 0; j < 4; j++) acc[i][j] = 0;

#pragma unroll 8
    for (int k = 0; k < 64; k++) {
        float4 a0 = *(const float4*)&AS(k, m0);
        float4 a1 = *(const float4*)&AS(k, m0 + 4);
        longlong2 bv0 = *(const longlong2*)&BS(k, n0);
        longlong2 bv1 = *(const longlong2*)&BS(k, n0 + 4);
        ull b[4] = {(ull)bv0.x, (ull)bv0.y, (ull)bv1.x, (ull)bv1.y};
        float am[8] = {a0.x, a0.y, a0.z, a0.w, a1.x, a1.y, a1.z, a1.w};
#pragma unroll
        for (int i = 0; i < 8; i++) {
            ull ad = pk2(am[i], am[i]);
            fma2(acc[i][0], b[0], ad);
            fma2(acc[i][1], b[1], ad);
            fma2(acc[i][2], b[2], ad);
            fma2(acc[i][3], b[3], ad);
        }
    }

    float4 bi0 = *(const float4*)&g_bias[col0 + n0];
    float4 bi1 = *(const float4*)&g_bias[col0 + n0 + 4];
    float bn[8] = {bi0.x, bi0.y, bi0.z, bi0.w, bi1.x, bi1.y, bi1.z, bi1.w};
#pragma unroll
    for (int i = 0; i < 8; i++) {
        float v[8];
        upk2(acc[i][0], v[0], v[1]); upk2(acc[i][1], v[2], v[3]);
        upk2(acc[i][2], v[4], v[5]); upk2(acc[i][3], v[6], v[7]);
        float* dst = &g_xg[(size_t)(row0 + m0 + i) * 512 + col0 + n0];
        *(float4*)dst       = make_float4(v[0] + bn[0], v[1] + bn[1], v[2] + bn[2], v[3] + bn[3]);
        *(float4*)(dst + 4) = make_float4(v[4] + bn[4], v[5] + bn[5], v[6] + bn[6], v[7] + bn[7]);
    }
}

// ---------------- persistent LSTM + FC (R2 structure: warp-uniform q) ----------------
#define LS_WS   0                        // 64*128 longlong2 (128 KB): W_hh k in [32q+16,32q+32)
#define LS_XB   (128 * 1024)             // 2*512 float4 (16 KB): xg double buffer
#define LS_PIF  (LS_XB + 16384)          // 16*128 ull (16 KB)
#define LS_PGO  (LS_PIF + 16384)         // 16*128 ull (16 KB)
#define LS_H    (LS_PGO + 16384)         // 512 float (2 KB): h[k][s]
#define LS_TOTAL (LS_H + 2048)           // 182272 B

__global__ void __launch_bounds__(512, 1) lstm_kernel(
    const float* __restrict__ Wfc, const float* __restrict__ bfc,
    float* __restrict__ out)
{
    extern __shared__ char smem[];
    longlong2* Ws2 = (longlong2*)(smem + LS_WS);
    float4*    xb4 = (float4*)(smem + LS_XB);
    ull*       pIF = (ull*)(smem + LS_PIF);
    ull*       pGO = (ull*)(smem + LS_PGO);
    float*     hsm = (float*)(smem + LS_H);
    const float4* hs4 = (const float4*)hsm;

    int tid = threadIdx.x;
    int r = tid & 127, q = tid >> 7;
    int s0 = blockIdx.x * 4;

    // register half of W_hh: k in [32q, 32q+16)
    ull WIF[16], WGO[16];
    const longlong2* Wp2 = (const longlong2*)g_Wp;
#pragma unroll
    for (int kk = 0; kk < 16; kk++) {
        longlong2 v = Wp2[(32 * q + kk) * 128 + r];
        WIF[kk] = (ull)v.x; WGO[kk] = (ull)v.y;
    }
    // smem half: k in [32q+16, 32q+32)
    for (int idx = tid; idx < 64 * 128; idx += 512) {
        int kidx = idx >> 7, rr = idx & 127;
        int qq = kidx >> 4, kk = (kidx & 15) + 16;
        Ws2[idx] = Wp2[(32 * qq + kk) * 128 + rr];
    }

    hsm[tid < 512 ? tid : 0] = 0.f;
    const float4* xg4 = (const float4*)g_xg;
    xb4[tid] = xg4[(size_t)s0 * 128 + tid];   // t=0 -> buffer 0

    float cst = 0.f;   // c-state for (row r, seq q)
    __syncthreads();

#pragma unroll 1
    for (int t = 0; t < TLEN; t++) {
        float4 nx = make_float4(0.f, 0.f, 0.f, 0.f);
        if (t + 1 < TLEN) nx = xg4[((size_t)(t + 1) * NSEQ + s0) * 128 + tid];

        ull aIF0 = 0, aIF1 = 0, aIF2 = 0, aIF3 = 0;
        ull aGO0 = 0, aGO1 = 0, aGO2 = 0, aGO3 = 0;

#pragma unroll
        for (int kk = 0; kk < 16; kk++) {            // register-W half
            float4 hv = hs4[32 * q + kk];            // uniform broadcast: 1 wf
            ull h0 = pk2(hv.x, hv.x), h1 = pk2(hv.y, hv.y);
            ull h2 = pk2(hv.z, hv.z), h3 = pk2(hv.w, hv.w);
            fma2(aIF0, WIF[kk], h0); fma2(aGO0, WGO[kk], h0);
            fma2(aIF1, WIF[kk], h1); fma2(aGO1, WGO[kk], h1);
            fma2(aIF2, WIF[kk], h2); fma2(aGO2, WGO[kk], h2);
            fma2(aIF3, WIF[kk], h3); fma2(aGO3, WGO[kk], h3);
        }
#pragma unroll
        for (int kk = 0; kk < 16; kk++) {            // smem-W half
            longlong2 wv = Ws2[(q * 16 + kk) * 128 + r];   // coalesced: 4 wf
            ull wIF = (ull)wv.x, wGO = (ull)wv.y;
            float4 hv = hs4[32 * q + 16 + kk];
            ull h0 = pk2(hv.x, hv.x), h1 = pk2(hv.y, hv.y);
            ull h2 = pk2(hv.z, hv.z), h3 = pk2(hv.w, hv.w);
            fma2(aIF0, wIF, h0); fma2(aGO0, wGO, h0);
            fma2(aIF1, wIF, h1); fma2(aGO1, wGO, h1);
            fma2(aIF2, wIF, h2); fma2(aGO2, wGO, h2);
            fma2(aIF3, wIF, h3); fma2(aGO3, wGO, h3);
        }

        // hoist gate-x loads (buffer t is stable since last barrier)
        const float* xb = (const float*)&xb4[(t & 1) * 512];
        float xi  = xb[q * 512 + r];
        float xf  = xb[q * 512 + 128 + r];
        float xgv = xb[q * 512 + 256 + r];
        float xo  = xb[q * 512 + 384 + r];

        pIF[(q * 4 + 0) * 128 + r] = aIF0;  pGO[(q * 4 + 0) * 128 + r] = aGO0;
        pIF[(q * 4 + 1) * 128 + r] = aIF1;  pGO[(q * 4 + 1) * 128 + r] = aGO1;
        pIF[(q * 4 + 2) * 128 + r] = aIF2;  pGO[(q * 4 + 2) * 128 + r] = aGO2;
        pIF[(q * 4 + 3) * 128 + r] = aIF3;  pGO[(q * 4 + 3) * 128 + r] = aGO3;
        if (t + 1 < TLEN) xb4[((t + 1) & 1) * 512 + tid] = nx;
        __syncthreads();

        // reduce 4 k-quarters + activations; thread owns (r, s=q)
        int s2 = q;
        ull sIF = pIF[s2 * 128 + r];
        add2(sIF, pIF[(4 + s2) * 128 + r]);
        add2(sIF, pIF[(8 + s2) * 128 + r]);
        add2(sIF, pIF[(12 + s2) * 128 + r]);
        ull sGO = pGO[s2 * 128 + r];
        add2(sGO, pGO[(4 + s2) * 128 + r]);
        add2(sGO, pGO[(8 + s2) * 128 + r]);
        add2(sGO, pGO[(12 + s2) * 128 + r]);

        float gi, gf, gg, go;
        upk2(sIF, gi, gf); upk2(sGO, gg, go);
        gi += xi; gf += xf; gg += xgv; go += xo;

        float i_ = 0.5f * tanh_t(0.5f * gi) + 0.5f;
        float f_ = 0.5f * tanh_t(0.5f * gf) + 0.5f;
        float o_ = 0.5f * tanh_t(0.5f * go) + 0.5f;
        float g_ = tanh_t(gg);

        cst = f_ * cst + i_ * g_;
        float th = tanh_t(cst);
        hsm[r * 4 + s2] = o_ * th;
        __syncthreads();
    }

    // ---- FC epilogue (reuse Ws2 region for transposed W_fc) ----
    float* wfs = (float*)(smem + LS_WS);
    for (int idx = tid; idx < CH * HID; idx += 512) {
        int c = idx >> 7, j = idx & 127;
        wfs[j * 64 + c] = Wfc[idx];
    }
    __syncthreads();
    if (tid < 256) {
        int c = tid & 63, s = tid >> 6;
        float acc = bfc[c];
#pragma unroll 8
        for (int j = 0; j < HID; j++)
            acc += hsm[j * 4 + s] * wfs[j * 64 + c];
        out[(s0 + s) * 64 + c] = acc;
    }
}

// ---------------- launch ----------------
extern "C" void kernel_launch(void* const* d_in, const int* in_sizes, int n_in,
                              void* d_out, int out_size)
{
    const float* x   = (const float*)d_in[0];
    const float* Wih = (const float*)d_in[1];
    const float* Whh = (const float*)d_in[2];
    const float* bih = (const float*)d_in[3];
    const float* bhh = (const float*)d_in[4];
    const float* Wfc = (const float*)d_in[5];
    const float* bfc = (const float*)d_in[6];
    float* out = (float*)d_out;

    cudaFuncSetAttribute(gemm_kernel, cudaFuncAttributeMaxDynamicSharedMemorySize, GEMM_SMEM);
    cudaFuncSetAttribute(lstm_kernel, cudaFuncAttributeMaxDynamicSharedMemorySize, LS_TOTAL);

    prep_kernel<<<256, 256>>>(Wih, Whh, bih, bhh);
    transp_kernel<<<dim3(TLEN, 16), 256>>>(x);
    gemm_kernel<<<dim3(NROW / 128, G4 / 128), 256, GEMM_SMEM>>>();
    lstm_kernel<<<120, 512, LS_TOTAL>>>(Wfc, bfc, out);
}

// round 9
// speedup vs baseline: 2.3861x; 1.1553x over previous
#include <cuda_runtime.h>
#include <cuda_bf16.h>
#include <cstdint>

typedef unsigned long long ull;

#define NSEQ 480
#define TLEN 200
#define CH   64
#define HID  128
#define G4   512
#define NROW (NSEQ * TLEN)   // 96000

// ---------------- device scratch ----------------
__device__ __nv_bfloat16 g_xh[NROW * CH];   // x hi split, [t*480+seq][c]
__device__ __nv_bfloat16 g_xl[NROW * CH];   // x lo split
__device__ __nv_bfloat16 g_Wh[G4 * CH];     // W_ih hi split, [g][c]
__device__ __nv_bfloat16 g_Wl[G4 * CH];     // W_ih lo split
__device__ float g_xg[NROW * G4];           // input gates [t*480+seq][g]
__device__ float g_Wp[HID * HID * 4];       // [k][r][{i,f,g,o}]
__device__ float g_bias[G4];

// ---------------- helpers ----------------
__device__ __forceinline__ ull pk2(float lo, float hi) {
    ull r; asm("mov.b64 %0, {%1, %2};" : "=l"(r) : "f"(lo), "f"(hi)); return r;
}
__device__ __forceinline__ void upk2(ull v, float& lo, float& hi) {
    asm("mov.b64 {%0, %1}, %2;" : "=f"(lo), "=f"(hi) : "l"(v));
}
__device__ __forceinline__ void fma2(ull& a, ull b, ull c) {
    asm("fma.rn.f32x2 %0, %1, %2, %0;" : "+l"(a) : "l"(b), "l"(c));
}
__device__ __forceinline__ void add2(ull& a, ull b) {
    asm("add.rn.f32x2 %0, %0, %1;" : "+l"(a) : "l"(b));
}
__device__ __forceinline__ float tanh_t(float x) {
    float t; asm("tanh.approx.f32 %0, %1;" : "=f"(t) : "f"(x)); return t;
}
__device__ __forceinline__ void mma16816(float* d, const uint32_t* a, uint32_t b0, uint32_t b1) {
    asm volatile(
        "mma.sync.aligned.m16n8k16.row.col.f32.bf16.bf16.f32 "
        "{%0,%1,%2,%3}, {%4,%5,%6,%7}, {%8,%9}, {%0,%1,%2,%3};"
        : "+f"(d[0]), "+f"(d[1]), "+f"(d[2]), "+f"(d[3])
        : "r"(a[0]), "r"(a[1]), "r"(a[2]), "r"(a[3]), "r"(b0), "r"(b1));
}

// ---------------- prep: W_hh pack, W_ih bf16 split, bias fold ----------------
__global__ void __launch_bounds__(256) prep_kernel(
    const float* __restrict__ Wih, const float* __restrict__ Whh,
    const float* __restrict__ bih, const float* __restrict__ bhh)
{
    int idx = blockIdx.x * 256 + threadIdx.x;
    if (idx < HID * HID * 4) {
        int qg = idx & 3, r = (idx >> 2) & 127, k = idx >> 9;
        g_Wp[idx] = Whh[(qg * 128 + r) * 128 + k];
    }
    if (idx < G4 * CH) {
        float w = Wih[idx];
        __nv_bfloat16 hi = __float2bfloat16(w);
        g_Wh[idx] = hi;
        g_Wl[idx] = __float2bfloat16(w - __bfloat162float(hi));
    }
    if (idx < G4) g_bias[idx] = bih[idx] + bhh[idx];
}

// ---------------- transpose + bf16 split: (B,C,T,P) -> xh/xl[t*480+b*30+p][c] ----------------
__global__ void __launch_bounds__(256) transp_kernel(const float* __restrict__ x)
{
    __shared__ float tile[64 * 30];
    int t = blockIdx.x, b = blockIdx.y;
    for (int idx = threadIdx.x; idx < 64 * 30; idx += 256) {
        int c = idx / 30, p = idx - c * 30;
        tile[idx] = x[(b * 64 + c) * 6000 + t * 30 + p];
    }
    __syncthreads();
    for (int idx = threadIdx.x; idx < 64 * 30; idx += 256) {
        int p = idx >> 6, c = idx & 63;
        float v = tile[c * 30 + p];
        __nv_bfloat16 hi = __float2bfloat16(v);
        int o = (t * NSEQ + b * 30 + p) * 64 + c;
        g_xh[o] = hi;
        g_xl[o] = __float2bfloat16(v - __bfloat162float(hi));
    }
}

// ---------------- HMMA GEMM: xg = split3(x @ Wih^T) + bias ----------------
// CTA tile: 128 rows x 128 cols, K=64. Grid (750, 4). 8 warps; warp w owns
// rows [w*16, w*16+16), all 128 cols (16 n-frags of m16n8k16).
// smem: A (xh,xl) 2 x 128 rows x 144B pad; B (Wh,Wl) same; bias 128 floats.
#define HG_B0   36864
#define HG_BIAS 73728
#define HG_SMEM 74240

__global__ void __launch_bounds__(256) hgemm_kernel()
{
    extern __shared__ char sm[];
    int tid = threadIdx.x, w = tid >> 5, l = tid & 31;
    int row0 = blockIdx.x * 128, col0 = blockIdx.y * 128;

    // stage A and B tiles into padded smem (144B rows)
    for (int i = tid; i < 4096; i += 256) {
        int isB = i >> 11;
        int j = i & 2047;
        int arr = j >> 10, rem = j & 1023, row = rem >> 3, ch = rem & 7;
        const uint4* src;
        size_t gidx;
        if (!isB) {
            src = arr ? (const uint4*)g_xl : (const uint4*)g_xh;
            gidx = (size_t)(row0 + row) * 8 + ch;
        } else {
            src = arr ? (const uint4*)g_Wl : (const uint4*)g_Wh;
            gidx = (size_t)(col0 + row) * 8 + ch;
        }
        *(uint4*)(sm + isB * 36864 + arr * 18432 + row * 144 + ch * 16) = src[gidx];
    }
    if (tid < 128) ((float*)(sm + HG_BIAS))[tid] = g_bias[col0 + tid];
    __syncthreads();

    int lr = l >> 2;          // 0..7
    int lc = (l & 3) * 2;     // half-index 0,2,4,6

    float acc[16][4];
#pragma unroll
    for (int nf = 0; nf < 16; nf++)
#pragma unroll
        for (int j = 0; j < 4; j++) acc[nf][j] = 0.f;

#pragma unroll
    for (int kf = 0; kf < 4; kf++) {
        int aoff = (w * 16 + lr) * 144 + (kf * 16 + lc) * 2;
        uint32_t ah[4], al[4];
        ah[0] = *(const uint32_t*)(sm + aoff);
        ah[1] = *(const uint32_t*)(sm + aoff + 8 * 144);
        ah[2] = *(const uint32_t*)(sm + aoff + 16);
        ah[3] = *(const uint32_t*)(sm + aoff + 8 * 144 + 16);
        al[0] = *(const uint32_t*)(sm + 18432 + aoff);
        al[1] = *(const uint32_t*)(sm + 18432 + aoff + 8 * 144);
        al[2] = *(const uint32_t*)(sm + 18432 + aoff + 16);
        al[3] = *(const uint32_t*)(sm + 18432 + aoff + 8 * 144 + 16);
#pragma unroll
        for (int nf = 0; nf < 16; nf++) {
            int boff = HG_B0 + (nf * 8 + lr) * 144 + (kf * 16 + lc) * 2;
            uint32_t bh0 = *(const uint32_t*)(sm + boff);
            uint32_t bh1 = *(const uint32_t*)(sm + boff + 16);
            uint32_t bl0 = *(const uint32_t*)(sm + boff + 18432);
            uint32_t bl1 = *(const uint32_t*)(sm + boff + 18432 + 16);
            mma16816(acc[nf], ah, bh0, bh1);
            mma16816(acc[nf], al, bh0, bh1);
            mma16816(acc[nf], ah, bl0, bl1);
        }
    }

    // epilogue: d-frag rows (w*16+lr, +8), cols nf*8 + lc + {0,1}; full 32B sectors
    const float* bs = (const float*)(sm + HG_BIAS);
    int rgA = row0 + w * 16 + lr;
#pragma unroll
    for (int nf = 0; nf < 16; nf++) {
        float b0 = bs[nf * 8 + lc], b1 = bs[nf * 8 + lc + 1];
        size_t cA = (size_t)rgA * 512 + col0 + nf * 8 + lc;
        float2 o0 = make_float2(acc[nf][0] + b0, acc[nf][1] + b1);
        float2 o1 = make_float2(acc[nf][2] + b0, acc[nf][3] + b1);
        *(float2*)&g_xg[cA] = o0;
        *(float2*)&g_xg[cA + 8 * 512] = o1;
    }
}

// ---------------- persistent LSTM + FC (R7, unchanged) ----------------
#define LS_WS   0
#define LS_XB   (128 * 1024)
#define LS_PIF  (LS_XB + 16384)
#define LS_PGO  (LS_PIF + 16384)
#define LS_H    (LS_PGO + 16384)
#define LS_TOTAL (LS_H + 2048)

__global__ void __launch_bounds__(512, 1) lstm_kernel(
    const float* __restrict__ Wfc, const float* __restrict__ bfc,
    float* __restrict__ out)
{
    extern __shared__ char smem[];
    longlong2* Ws2 = (longlong2*)(smem + LS_WS);
    float4*    xb4 = (float4*)(smem + LS_XB);
    ull*       pIF = (ull*)(smem + LS_PIF);
    ull*       pGO = (ull*)(smem + LS_PGO);
    float*     hsm = (float*)(smem + LS_H);
    const float4* hs4 = (const float4*)hsm;

    int tid = threadIdx.x;
    int r = tid & 127, q = tid >> 7;
    int s0 = blockIdx.x * 4;

    ull WIF[16], WGO[16];
    const longlong2* Wp2 = (const longlong2*)g_Wp;
#pragma unroll
    for (int kk = 0; kk < 16; kk++) {
        longlong2 v = Wp2[(32 * q + kk) * 128 + r];
        WIF[kk] = (ull)v.x; WGO[kk] = (ull)v.y;
    }
    for (int idx = tid; idx < 64 * 128; idx += 512) {
        int kidx = idx >> 7, rr = idx & 127;
        int qq = kidx >> 4, kk = (kidx & 15) + 16;
        Ws2[idx] = Wp2[(32 * qq + kk) * 128 + rr];
    }

    hsm[tid < 512 ? tid : 0] = 0.f;
    const float4* xg4 = (const float4*)g_xg;
    xb4[tid] = xg4[(size_t)s0 * 128 + tid];

    float cst = 0.f;
    __syncthreads();

#pragma unroll 1
    for (int t = 0; t < TLEN; t++) {
        float4 nx = make_float4(0.f, 0.f, 0.f, 0.f);
        if (t + 1 < TLEN) nx = xg4[((size_t)(t + 1) * NSEQ + s0) * 128 + tid];

        ull aIF0 = 0, aIF1 = 0, aIF2 = 0, aIF3 = 0;
        ull aGO0 = 0, aGO1 = 0, aGO2 = 0, aGO3 = 0;

#pragma unroll
        for (int kk = 0; kk < 16; kk++) {
            float4 hv = hs4[32 * q + kk];
            ull h0 = pk2(hv.x, hv.x), h1 = pk2(hv.y, hv.y);
            ull h2 = pk2(hv.z, hv.z), h3 = pk2(hv.w, hv.w);
            fma2(aIF0, WIF[kk], h0); fma2(aGO0, WGO[kk], h0);
            fma2(aIF1, WIF[kk], h1); fma2(aGO1, WGO[kk], h1);
            fma2(aIF2, WIF[kk], h2); fma2(aGO2, WGO[kk], h2);
            fma2(aIF3, WIF[kk], h3); fma2(aGO3, WGO[kk], h3);
        }
#pragma unroll
        for (int kk = 0; kk < 16; kk++) {
            longlong2 wv = Ws2[(q * 16 + kk) * 128 + r];
            ull wIF = (ull)wv.x, wGO = (ull)wv.y;
            float4 hv = hs4[32 * q + 16 + kk];
            ull h0 = pk2(hv.x, hv.x), h1 = pk2(hv.y, hv.y);
            ull h2 = pk2(hv.z, hv.z), h3 = pk2(hv.w, hv.w);
            fma2(aIF0, wIF, h0); fma2(aGO0, wGO, h0);
            fma2(aIF1, wIF, h1); fma2(aGO1, wGO, h1);
            fma2(aIF2, wIF, h2); fma2(aGO2, wGO, h2);
            fma2(aIF3, wIF, h3); fma2(aGO3, wGO, h3);
        }

        const float* xb = (const float*)&xb4[(t & 1) * 512];
        float xi  = xb[q * 512 + r];
        float xf  = xb[q * 512 + 128 + r];
        float xgv = xb[q * 512 + 256 + r];
        float xo  = xb[q * 512 + 384 + r];

        pIF[(q * 4 + 0) * 128 + r] = aIF0;  pGO[(q * 4 + 0) * 128 + r] = aGO0;
        pIF[(q * 4 + 1) * 128 + r] = aIF1;  pGO[(q * 4 + 1) * 128 + r] = aGO1;
        pIF[(q * 4 + 2) * 128 + r] = aIF2;  pGO[(q * 4 + 2) * 128 + r] = aGO2;
        pIF[(q * 4 + 3) * 128 + r] = aIF3;  pGO[(q * 4 + 3) * 128 + r] = aGO3;
        if (t + 1 < TLEN) xb4[((t + 1) & 1) * 512 + tid] = nx;
        __syncthreads();

        int s2 = q;
        ull sIF = pIF[s2 * 128 + r];
        add2(sIF, pIF[(4 + s2) * 128 + r]);
        add2(sIF, pIF[(8 + s2) * 128 + r]);
        add2(sIF, pIF[(12 + s2) * 128 + r]);
        ull sGO = pGO[s2 * 128 + r];
        add2(sGO, pGO[(4 + s2) * 128 + r]);
        add2(sGO, pGO[(8 + s2) * 128 + r]);
        add2(sGO, pGO[(12 + s2) * 128 + r]);

        float gi, gf, gg, go;
        upk2(sIF, gi, gf); upk2(sGO, gg, go);
        gi += xi; gf += xf; gg += xgv; go += xo;

        float i_ = 0.5f * tanh_t(0.5f * gi) + 0.5f;
        float f_ = 0.5f * tanh_t(0.5f * gf) + 0.5f;
        float o_ = 0.5f * tanh_t(0.5f * go) + 0.5f;
        float g_ = tanh_t(gg);

        cst = f_ * cst + i_ * g_;
        float th = tanh_t(cst);
        hsm[r * 4 + s2] = o_ * th;
        __syncthreads();
    }

    float* wfs = (float*)(smem + LS_WS);
    for (int idx = tid; idx < CH * HID; idx += 512) {
        int c = idx >> 7, j = idx & 127;
        wfs[j * 64 + c] = Wfc[idx];
    }
    __syncthreads();
    if (tid < 256) {
        int c = tid & 63, s = tid >> 6;
        float acc = bfc[c];
#pragma unroll 8
        for (int j = 0; j < HID; j++)
            acc += hsm[j * 4 + s] * wfs[j * 64 + c];
        out[(s0 + s) * 64 + c] = acc;
    }
}

// ---------------- launch ----------------
extern "C" void kernel_launch(void* const* d_in, const int* in_sizes, int n_in,
                              void* d_out, int out_size)
{
    const float* x   = (const float*)d_in[0];
    const float* Wih = (const float*)d_in[1];
    const float* Whh = (const float*)d_in[2];
    const float* bih = (const float*)d_in[3];
    const float* bhh = (const float*)d_in[4];
    const float* Wfc = (const float*)d_in[5];
    const float* bfc = (const float*)d_in[6];
    float* out = (float*)d_out;

    cudaFuncSetAttribute(hgemm_kernel, cudaFuncAttributeMaxDynamicSharedMemorySize, HG_SMEM);
    cudaFuncSetAttribute(lstm_kernel, cudaFuncAttributeMaxDynamicSharedMemorySize, LS_TOTAL);

    prep_kernel<<<256, 256>>>(Wih, Whh, bih, bhh);
    transp_kernel<<<dim3(TLEN, 16), 256>>>(x);
    hgemm_kernel<<<dim3(NROW / 128, 4), 256, HG_SMEM>>>();
    lstm_kernel<<<120, 512, LS_TOTAL>>>(Wfc, bfc, out);
}

// round 10
// speedup vs baseline: 2.6619x; 1.1156x over previous
#include <cuda_runtime.h>
#include <cuda_bf16.h>
#include <cstdint>

typedef unsigned long long ull;

#define NSEQ 480
#define TLEN 200
#define CH   64
#define HID  128
#define G4   512
#define NROW (NSEQ * TLEN)   // 96000

// ---------------- device scratch ----------------
__device__ __nv_bfloat16 g_xh[NROW * CH];    // x hi split, [t*480+seq][c]
__device__ __nv_bfloat16 g_xl[NROW * CH];    // x lo split
__device__ __nv_bfloat16 g_Wh[G4 * CH];      // W_ih hi split, [g][c]
__device__ __nv_bfloat16 g_Wl[G4 * CH];      // W_ih lo split
__device__ __nv_bfloat16 g_WhhHi[G4 * HID];  // W_hh hi split, [g][k]
__device__ __nv_bfloat16 g_WhhLo[G4 * HID];  // W_hh lo split
__device__ float g_xg[NROW * G4];            // input gates [t*480+seq][g]
__device__ float g_bias[G4];

// ---------------- helpers ----------------
__device__ __forceinline__ float tanh_t(float x) {
    float t; asm("tanh.approx.f32 %0, %1;" : "=f"(t) : "f"(x)); return t;
}
__device__ __forceinline__ uint32_t smem_u32(const void* p) {
    uint32_t a;
    asm("{ .reg .u64 t; cvta.to.shared.u64 t, %1; cvt.u32.u64 %0, t; }" : "=r"(a) : "l"(p));
    return a;
}
__device__ __forceinline__ void mma16816(float* d, const uint32_t* a, uint32_t b0, uint32_t b1) {
    asm volatile(
        "mma.sync.aligned.m16n8k16.row.col.f32.bf16.bf16.f32 "
        "{%0,%1,%2,%3}, {%4,%5,%6,%7}, {%8,%9}, {%0,%1,%2,%3};"
        : "+f"(d[0]), "+f"(d[1]), "+f"(d[2]), "+f"(d[3])
        : "r"(a[0]), "r"(a[1]), "r"(a[2]), "r"(a[3]), "r"(b0), "r"(b1));
}

// ---------------- prep: bf16 splits + bias fold ----------------
__global__ void __launch_bounds__(256) prep_kernel(
    const float* __restrict__ Wih, const float* __restrict__ Whh,
    const float* __restrict__ bih, const float* __restrict__ bhh)
{
    int idx = blockIdx.x * 256 + threadIdx.x;
    if (idx < G4 * HID) {
        float w = Whh[idx];
        __nv_bfloat16 hi = __float2bfloat16(w);
        g_WhhHi[idx] = hi;
        g_WhhLo[idx] = __float2bfloat16(w - __bfloat162float(hi));
    }
    if (idx < G4 * CH) {
        float w = Wih[idx];
        __nv_bfloat16 hi = __float2bfloat16(w);
        g_Wh[idx] = hi;
        g_Wl[idx] = __float2bfloat16(w - __bfloat162float(hi));
    }
    if (idx < G4) g_bias[idx] = bih[idx] + bhh[idx];
}

// ---------------- transpose + bf16 split ----------------
__global__ void __launch_bounds__(256) transp_kernel(const float* __restrict__ x)
{
    __shared__ float tile[64 * 30];
    int t = blockIdx.x, b = blockIdx.y;
    for (int idx = threadIdx.x; idx < 64 * 30; idx += 256) {
        int c = idx / 30, p = idx - c * 30;
        tile[idx] = x[(b * 64 + c) * 6000 + t * 30 + p];
    }
    __syncthreads();
    for (int idx = threadIdx.x; idx < 64 * 30; idx += 256) {
        int p = idx >> 6, c = idx & 63;
        float v = tile[c * 30 + p];
        __nv_bfloat16 hi = __float2bfloat16(v);
        int o = (t * NSEQ + b * 30 + p) * 64 + c;
        g_xh[o] = hi;
        g_xl[o] = __float2bfloat16(v - __bfloat162float(hi));
    }
}

// ---------------- HMMA GEMM: xg = split3(x @ Wih^T) + bias (R9, unchanged) ----------------
#define HG_B0   36864
#define HG_BIAS 73728
#define HG_SMEM 74240

__global__ void __launch_bounds__(256) hgemm_kernel()
{
    extern __shared__ char sm[];
    int tid = threadIdx.x, w = tid >> 5, l = tid & 31;
    int row0 = blockIdx.x * 128, col0 = blockIdx.y * 128;

    for (int i = tid; i < 4096; i += 256) {
        int isB = i >> 11;
        int j = i & 2047;
        int arr = j >> 10, rem = j & 1023, row = rem >> 3, ch = rem & 7;
        const uint4* src;
        size_t gidx;
        if (!isB) {
            src = arr ? (const uint4*)g_xl : (const uint4*)g_xh;
            gidx = (size_t)(row0 + row) * 8 + ch;
        } else {
            src = arr ? (const uint4*)g_Wl : (const uint4*)g_Wh;
            gidx = (size_t)(col0 + row) * 8 + ch;
        }
        *(uint4*)(sm + isB * 36864 + arr * 18432 + row * 144 + ch * 16) = src[gidx];
    }
    if (tid < 128) ((float*)(sm + HG_BIAS))[tid] = g_bias[col0 + tid];
    __syncthreads();

    int lr = l >> 2;
    int lc = (l & 3) * 2;

    float acc[16][4];
#pragma unroll
    for (int nf = 0; nf < 16; nf++)
#pragma unroll
        for (int j = 0; j < 4; j++) acc[nf][j] = 0.f;

#pragma unroll
    for (int kf = 0; kf < 4; kf++) {
        int aoff = (w * 16 + lr) * 144 + (kf * 16 + lc) * 2;
        uint32_t ah[4], al[4];
        ah[0] = *(const uint32_t*)(sm + aoff);
        ah[1] = *(const uint32_t*)(sm + aoff + 8 * 144);
        ah[2] = *(const uint32_t*)(sm + aoff + 16);
        ah[3] = *(const uint32_t*)(sm + aoff + 8 * 144 + 16);
        al[0] = *(const uint32_t*)(sm + 18432 + aoff);
        al[1] = *(const uint32_t*)(sm + 18432 + aoff + 8 * 144);
        al[2] = *(const uint32_t*)(sm + 18432 + aoff + 16);
        al[3] = *(const uint32_t*)(sm + 18432 + aoff + 8 * 144 + 16);
#pragma unroll
        for (int nf = 0; nf < 16; nf++) {
            int boff = HG_B0 + (nf * 8 + lr) * 144 + (kf * 16 + lc) * 2;
            uint32_t bh0 = *(const uint32_t*)(sm + boff);
            uint32_t bh1 = *(const uint32_t*)(sm + boff + 16);
            uint32_t bl0 = *(const uint32_t*)(sm + boff + 18432);
            uint32_t bl1 = *(const uint32_t*)(sm + boff + 18432 + 16);
            mma16816(acc[nf], ah, bh0, bh1);
            mma16816(acc[nf], al, bh0, bh1);
            mma16816(acc[nf], ah, bl0, bl1);
        }
    }

    const float* bs = (const float*)(sm + HG_BIAS);
    int rgA = row0 + w * 16 + lr;
#pragma unroll
    for (int nf = 0; nf < 16; nf++) {
        float b0 = bs[nf * 8 + lc], b1 = bs[nf * 8 + lc + 1];
        size_t cA = (size_t)rgA * 512 + col0 + nf * 8 + lc;
        *(float2*)&g_xg[cA] = make_float2(acc[nf][0] + b0, acc[nf][1] + b1);
        *(float2*)&g_xg[cA + 8 * 512] = make_float2(acc[nf][2] + b0, acc[nf][3] + b1);
    }
}

// ---------------- persistent LSTM via HMMA + FC ----------------
// 120 CTAs x 256 threads (8 warps). 4 real seqs/CTA, padded to N=8.
// G[512][8] = Whh[512][128] @ h[128][8]; warp w owns gate rows [64w, 64w+64).
// smem map (bytes):
#define L2_WLO 0                       // WhhLo padded: 512 rows x 272 B = 139264
#define L2_GAT 139264                  // gates: 512 x 9 floats = 18432
#define L2_XB  158720                  // xg double buf: 2 x 4x520 floats = 16640 (starts 16-aligned)
#define L2_HB  175360                  // h bf16 hi/lo, 2 bufs x (8x272 hi + 8x272 lo) = 8704
#define L2_HF  184064                  // h fp32 [128][4] = 2048
#define L2_TOTAL 186112

__global__ void __launch_bounds__(256) lstm2_kernel(
    const float* __restrict__ Wfc, const float* __restrict__ bfc,
    float* __restrict__ out)
{
    extern __shared__ char sm[];
    int tid = threadIdx.x, w = tid >> 5, l = tid & 31;
    int s0 = blockIdx.x * 4;
    uint32_t smb = smem_u32(sm);

    // stage WhhLo into 272-B padded rows
    {
        const uint32_t* wlo = (const uint32_t*)g_WhhLo;  // [512][64] u32
        for (int i = tid; i < 512 * 64; i += 256) {
            int row = i >> 6, cp = i & 63;
            *(uint32_t*)(sm + L2_WLO + row * 272 + cp * 4) = wlo[row * 64 + cp];
        }
    }
    // zero h buffers
    for (int i = tid; i < 8704 / 4; i += 256) ((uint32_t*)(sm + L2_HB))[i] = 0;
    // preload xb t=0 (buffer 0)
    const float4* xg4 = (const float4*)g_xg;
    for (int i = tid; i < 512; i += 256) {
        int s = i >> 7, g4i = i & 127;
        *(float4*)(sm + L2_XB + (s * 520 + g4i * 4) * 4) = xg4[(size_t)(s0 + s) * 128 + g4i];
    }

    // WhhHi fragments -> registers: WH[mf][kf][4]
    uint32_t WH[4][8][4];
    {
        const uint32_t* whi = (const uint32_t*)g_WhhHi;  // [512][64] u32
        int lr = l >> 2, lc = l & 3;
#pragma unroll
        for (int mf = 0; mf < 4; mf++)
#pragma unroll
            for (int kf = 0; kf < 8; kf++) {
                int row = w * 64 + mf * 16 + lr;
                int kc = kf * 8 + lc;
                WH[mf][kf][0] = whi[row * 64 + kc];
                WH[mf][kf][1] = whi[(row + 8) * 64 + kc];
                WH[mf][kf][2] = whi[row * 64 + kc + 4];
                WH[mf][kf][3] = whi[(row + 8) * 64 + kc + 4];
            }
    }
    __syncthreads();

    // ldmatrix lane base for WhhLo A-frags
    int lm = l >> 3, lr8 = l & 7;
    uint32_t wloBase = smb + L2_WLO
        + (uint32_t)((w * 64 + (lm & 1) * 8 + lr8) * 272 + ((lm >> 1) * 8) * 2);
    // B-frag lane base (h hi, buffer 0)
    uint32_t hbA = smb + L2_HB + (uint32_t)((l >> 2) * 272 + (l & 3) * 4);

    float cst0 = 0.f, cst1 = 0.f;
    int rC = tid & 127, sB = tid >> 7;

#pragma unroll 1
    for (int t = 0; t < TLEN; t++) {
        bool pf = (t + 1 < TLEN);
        float4 nx0, nx1;
        if (pf) {
            nx0 = xg4[(size_t)((t + 1) * NSEQ + s0 + sB) * 128 + rC];
            nx1 = xg4[(size_t)((t + 1) * NSEQ + s0 + sB + 2) * 128 + rC];
        }

        uint32_t hcur = hbA + (t & 1) * 4352;
        float acc[4][4];
#pragma unroll
        for (int mf = 0; mf < 4; mf++) {
            acc[mf][0] = 0.f; acc[mf][1] = 0.f; acc[mf][2] = 0.f; acc[mf][3] = 0.f;
        }

#pragma unroll
        for (int kf = 0; kf < 8; kf++) {
            uint32_t bh0, bh1, bl0, bl1;
            uint32_t ka = hcur + kf * 32;
            asm volatile("ld.shared.b32 %0, [%1];" : "=r"(bh0) : "r"(ka));
            asm volatile("ld.shared.b32 %0, [%1];" : "=r"(bh1) : "r"(ka + 16));
            asm volatile("ld.shared.b32 %0, [%1];" : "=r"(bl0) : "r"(ka + 2176));
            asm volatile("ld.shared.b32 %0, [%1];" : "=r"(bl1) : "r"(ka + 2192));
#pragma unroll
            for (int mf = 0; mf < 4; mf++) {
                uint32_t wl0, wl1, wl2, wl3;
                uint32_t la = wloBase + mf * (16 * 272) + kf * 32;
                asm volatile("ldmatrix.sync.aligned.m8n8.x4.shared.b16 {%0,%1,%2,%3}, [%4];"
                    : "=r"(wl0), "=r"(wl1), "=r"(wl2), "=r"(wl3) : "r"(la));
                uint32_t wl[4] = {wl0, wl1, wl2, wl3};
                mma16816(acc[mf], WH[mf][kf], bh0, bh1);
                mma16816(acc[mf], WH[mf][kf], bl0, bl1);
                mma16816(acc[mf], wl, bh0, bh1);
            }
        }

        // gate exchange: only seq cols 0-3 are real -> lanes with (l&3)<2
        if ((l & 3) < 2) {
            int c0 = (l & 3) * 2;
            float* gs = (float*)(sm + L2_GAT);
#pragma unroll
            for (int mf = 0; mf < 4; mf++) {
                int row = w * 64 + mf * 16 + (l >> 2);
                gs[row * 9 + c0]     = acc[mf][0];
                gs[row * 9 + c0 + 1] = acc[mf][1];
                gs[(row + 8) * 9 + c0]     = acc[mf][2];
                gs[(row + 8) * 9 + c0 + 1] = acc[mf][3];
            }
        }
        if (pf) {
            float* xd = (float*)(sm + L2_XB + ((t + 1) & 1) * 8320);
            *(float4*)&xd[sB * 520 + rC * 4] = nx0;
            *(float4*)&xd[(sB + 2) * 520 + rC * 4] = nx1;
        }
        __syncthreads();

        // consumer: activations for (rC, s) with s in {sB, sB+2}
        {
            const float* gs = (const float*)(sm + L2_GAT);
            const float* xbc = (const float*)(sm + L2_XB + (t & 1) * 8320);
            char* hn = sm + L2_HB + ((t + 1) & 1) * 4352;
            float* hf = (float*)(sm + L2_HF);
#pragma unroll
            for (int j = 0; j < 2; j++) {
                int s = sB + 2 * j;
                float& cr = j ? cst1 : cst0;
                float gi = gs[rC * 9 + s]           + xbc[s * 520 + rC];
                float gf = gs[(128 + rC) * 9 + s]   + xbc[s * 520 + 128 + rC];
                float gg = gs[(256 + rC) * 9 + s]   + xbc[s * 520 + 256 + rC];
                float go = gs[(384 + rC) * 9 + s]   + xbc[s * 520 + 384 + rC];
                float i_ = 0.5f * tanh_t(0.5f * gi) + 0.5f;
                float f_ = 0.5f * tanh_t(0.5f * gf) + 0.5f;
                float o_ = 0.5f * tanh_t(0.5f * go) + 0.5f;
                float g_ = tanh_t(gg);
                cr = f_ * cr + i_ * g_;
                float h = o_ * tanh_t(cr);
                __nv_bfloat16 hi = __float2bfloat16(h);
                float lo = h - __bfloat162float(hi);
                *(__nv_bfloat16*)(hn + s * 272 + rC * 2) = hi;
                *(__nv_bfloat16*)(hn + 2176 + s * 272 + rC * 2) = __float2bfloat16(lo);
                hf[rC * 4 + s] = h;
            }
        }
        __syncthreads();
    }

    // ---- FC epilogue: reuse WLO region for W_fc^T ----
    float* wfs = (float*)sm;
    for (int idx = tid; idx < CH * HID; idx += 256) {
        int c = idx >> 7, j = idx & 127;
        wfs[j * 64 + c] = Wfc[idx];
    }
    __syncthreads();
    {
        int c = tid & 63, s = tid >> 6;
        float accf = bfc[c];
        const float* hf = (const float*)(sm + L2_HF);
#pragma unroll 8
        for (int j = 0; j < HID; j++)
            accf += hf[j * 4 + s] * wfs[j * 64 + c];
        out[(s0 + s) * 64 + c] = accf;
    }
}

// ---------------- launch ----------------
extern "C" void kernel_launch(void* const* d_in, const int* in_sizes, int n_in,
                              void* d_out, int out_size)
{
    const float* x   = (const float*)d_in[0];
    const float* Wih = (const float*)d_in[1];
    const float* Whh = (const float*)d_in[2];
    const float* bih = (const float*)d_in[3];
    const float* bhh = (const float*)d_in[4];
    const float* Wfc = (const float*)d_in[5];
    const float* bfc = (const float*)d_in[6];
    float* out = (float*)d_out;

    cudaFuncSetAttribute(hgemm_kernel, cudaFuncAttributeMaxDynamicSharedMemorySize, HG_SMEM);
    cudaFuncSetAttribute(lstm2_kernel, cudaFuncAttributeMaxDynamicSharedMemorySize, L2_TOTAL);

    prep_kernel<<<256, 256>>>(Wih, Whh, bih, bhh);
    transp_kernel<<<dim3(TLEN, 16), 256>>>(x);
    hgemm_kernel<<<dim3(NROW / 128, 4), 256, HG_SMEM>>>();
    lstm2_kernel<<<120, 256, L2_TOTAL>>>(Wfc, bfc, out);
}